// round 7
// baseline (speedup 1.0000x reference)
#include <cuda_runtime.h>
#include <string.h>

#define NN 50000
#define NE 800000
#define H  128
#define NG 512

typedef unsigned long long ull;

// ---------------- scratch (static device globals; no allocation) ----------------
__device__ int   g_degi[NN];
__device__ float g_deginv[NN];
__device__ int   g_rowptr[NN + 1];
__device__ int   g_cursor[NN];
__device__ int   g_esrc[NE];                      // CSR: source node per in-edge
__device__ float g_xa[(size_t)NN * H];
__device__ float g_xb[(size_t)NN * H];
__device__ float g_pool[NG * H];

// ---------------- helpers ----------------
__device__ __forceinline__ void red4(float* p, float4 v) {
    asm volatile("red.global.add.v4.f32 [%0], {%1, %2, %3, %4};"
                 :: "l"(p), "f"(v.x), "f"(v.y), "f"(v.z), "f"(v.w) : "memory");
}

__device__ __forceinline__ ull dup2(float a) {
    ull r;
    asm("mov.b64 %0, {%1, %1};" : "=l"(r) : "f"(a));
    return r;
}

__device__ __forceinline__ ull pack2(float lo, float hi) {
    ull r;
    asm("mov.b64 %0, {%1, %2};" : "=l"(r) : "f"(lo), "f"(hi));
    return r;
}

__device__ __forceinline__ void unpack2(ull v, float& lo, float& hi) {
    asm("mov.b64 {%0, %1}, %2;" : "=f"(lo), "=f"(hi) : "l"(v));
}

__device__ __forceinline__ ull fma2(ull a, ull b, ull c) {
    ull d;
    asm("fma.rn.f32x2 %0, %1, %2, %3;" : "=l"(d) : "l"(a), "l"(b), "l"(c));
    return d;
}

__device__ __forceinline__ float4 f4add(float4 a, float4 b) {
    return make_float4(a.x + b.x, a.y + b.y, a.z + b.z, a.w + b.w);
}

// ---------------- setup kernels ----------------

__global__ void init_kernel() {
    int i = blockIdx.x * blockDim.x + threadIdx.x;
    if (i < NN) g_degi[i] = 0;
    if (i < NG * H) g_pool[i] = 0.0f;   // NG*H = 65536 >= NN
}

__global__ void deg_kernel(const int* __restrict__ dst) {
    int e = blockIdx.x * blockDim.x + threadIdx.x;
    if (e < NE) atomicAdd(&g_degi[dst[e]], 1);
}

#define SCAN_T 1024
__global__ void scan_kernel() {
    __shared__ int sm[SCAN_T];
    int t = threadIdx.x;
    const int C = (NN + SCAN_T - 1) / SCAN_T;   // 49
    int b = t * C;
    int e = b + C; if (e > NN) e = NN;
    if (b > NN) b = NN;
    int s = 0;
    for (int i = b; i < e; i++) s += g_degi[i];
    sm[t] = s;
    __syncthreads();
    for (int off = 1; off < SCAN_T; off <<= 1) {
        int v = (t >= off) ? sm[t - off] : 0;
        __syncthreads();
        sm[t] += v;
        __syncthreads();
    }
    int base = (t > 0) ? sm[t - 1] : 0;   // exclusive prefix
    for (int i = b; i < e; i++) {
        g_rowptr[i] = base;
        g_cursor[i] = base;
        int d = g_degi[i];
        g_deginv[i] = 1.0f / fmaxf((float)d, 1.0f);
        base += d;
    }
    if (t == SCAN_T - 1) g_rowptr[NN] = base;
}

__global__ void fill_kernel(const int* __restrict__ src, const int* __restrict__ dst) {
    int e = blockIdx.x * blockDim.x + threadIdx.x;
    if (e < NE) {
        int p = atomicAdd(&g_cursor[dst[e]], 1);
        g_esrc[p] = src[e];
    }
}

__global__ void embed_kernel(const int* __restrict__ z, const float* __restrict__ z_emb) {
    int idx = blockIdx.x * blockDim.x + threadIdx.x;
    if (idx >= NN * 32) return;
    int node = idx >> 5, lane = idx & 31;
    float4 v = *reinterpret_cast<const float4*>(z_emb + (size_t)z[node] * H + lane * 4);
    *reinterpret_cast<float4*>(g_xa + (size_t)node * H + lane * 4) = v;
}

// ---------------- fused SAGE layer ----------------
// Tile 64 rows x 128 cols, 256 threads (8 warps x 8 rows = 4 row-pairs each).
// A/X tiles stored TRANSPOSED as row-pair f32x2: T[k][rp] -> one broadcast LDS.64
// feeds FFMA2 directly (no operand duplication). W staged in smem per 32-k chunk;
// only W needs dup2 (per-k, per-col — 4x fewer MOVs than per-row duplication).

#define SP 33            // ull stride per k (32 pairs + 1 pad)
#define KC 32            // k-chunk for W staging
#define SMEM_BYTES (2 * 128 * SP * 8 + 2 * KC * H * 4)   // 67584 + 32768 = 100352

__device__ __forceinline__ float4 gather_row(const float* __restrict__ x, int row, int col) {
    float4 a0 = make_float4(0, 0, 0, 0);
    float4 a1 = a0, a2 = a0, a3 = a0;
    int beg = g_rowptr[row];
    int end = g_rowptr[row + 1];
    int e = beg;
    for (; e + 4 <= end; e += 4) {
        int s0 = g_esrc[e];
        int s1 = g_esrc[e + 1];
        int s2 = g_esrc[e + 2];
        int s3 = g_esrc[e + 3];
        a0 = f4add(a0, *reinterpret_cast<const float4*>(x + (size_t)s0 * H + col));
        a1 = f4add(a1, *reinterpret_cast<const float4*>(x + (size_t)s1 * H + col));
        a2 = f4add(a2, *reinterpret_cast<const float4*>(x + (size_t)s2 * H + col));
        a3 = f4add(a3, *reinterpret_cast<const float4*>(x + (size_t)s3 * H + col));
    }
    for (; e < end; e++) {
        int s0 = g_esrc[e];
        a0 = f4add(a0, *reinterpret_cast<const float4*>(x + (size_t)s0 * H + col));
    }
    float di = g_deginv[row];
    a0 = f4add(f4add(a0, a1), f4add(a2, a3));
    a0.x *= di; a0.y *= di; a0.z *= di; a0.w *= di;
    return a0;
}

template <bool RELU>
__global__ void __launch_bounds__(256)
sage_layer_kernel(const float* __restrict__ x,
                  const float* __restrict__ Wl,
                  const float* __restrict__ bl,
                  const float* __restrict__ Wr,
                  float* __restrict__ out) {
    extern __shared__ ull smu[];
    ull*   Asp = smu;                    // [128][SP] row-pair-packed agg (transposed)
    ull*   Xsp = smu + 128 * SP;         // [128][SP] row-pair-packed x  (transposed)
    float* Wls = (float*)(smu + 2 * 128 * SP);   // [KC][H]
    float* Wrs = Wls + KC * H;                   // [KC][H]

    int row0 = blockIdx.x * 64;
    int tid  = threadIdx.x;
    int lane = tid & 31;
    int w    = tid >> 5;
    int col  = lane * 4;
    int rpb  = w * 4;                    // this warp's first row-pair in tile

    // ---- gather + transpose-stage (own-warp rows only; no cross-warp deps) ----
    #pragma unroll 1
    for (int p = 0; p < 4; p++) {
        int rp = rpb + p;
        int re = row0 + rp * 2;
        int ro = re + 1;
        float4 xe = make_float4(0, 0, 0, 0), xo = xe, ae = xe, ao = xe;
        if (re < NN) {
            xe = *reinterpret_cast<const float4*>(x + (size_t)re * H + col);
            ae = gather_row(x, re, col);
        }
        if (ro < NN) {
            xo = *reinterpret_cast<const float4*>(x + (size_t)ro * H + col);
            ao = gather_row(x, ro, col);
        }
        Asp[(col + 0) * SP + rp] = pack2(ae.x, ao.x);
        Asp[(col + 1) * SP + rp] = pack2(ae.y, ao.y);
        Asp[(col + 2) * SP + rp] = pack2(ae.z, ao.z);
        Asp[(col + 3) * SP + rp] = pack2(ae.w, ao.w);
        Xsp[(col + 0) * SP + rp] = pack2(xe.x, xo.x);
        Xsp[(col + 1) * SP + rp] = pack2(xe.y, xo.y);
        Xsp[(col + 2) * SP + rp] = pack2(xe.z, xo.z);
        Xsp[(col + 3) * SP + rp] = pack2(xe.w, xo.w);
    }

    // ---- accumulators: acc[p][c] packs rows (2p, 2p+1) of column col+c ----
    ull acc[4][4];
    {
        float4 bv = *reinterpret_cast<const float4*>(bl + col);
        #pragma unroll
        for (int p = 0; p < 4; p++) {
            acc[p][0] = dup2(bv.x);
            acc[p][1] = dup2(bv.y);
            acc[p][2] = dup2(bv.z);
            acc[p][3] = dup2(bv.w);
        }
    }

    // ---- mainloop: W chunk-staged in smem, A/X via broadcast LDS.64 ----
    for (int kc = 0; kc < H / KC; kc++) {
        __syncthreads();   // previous chunk fully consumed before overwrite
        {
            const float4* wlg = reinterpret_cast<const float4*>(Wl + kc * KC * H);
            const float4* wrg = reinterpret_cast<const float4*>(Wr + kc * KC * H);
            float4* wls4 = reinterpret_cast<float4*>(Wls);
            float4* wrs4 = reinterpret_cast<float4*>(Wrs);
            #pragma unroll
            for (int i = tid; i < KC * H / 4; i += 256) {
                wls4[i] = wlg[i];
                wrs4[i] = wrg[i];
            }
        }
        __syncthreads();

        #pragma unroll 2
        for (int kk = 0; kk < KC; kk++) {
            int k = kc * KC + kk;
            float4 wl = *reinterpret_cast<const float4*>(&Wls[kk * H + col]);
            float4 wr = *reinterpret_cast<const float4*>(&Wrs[kk * H + col]);
            ull wl2[4], wr2[4];
            wl2[0] = dup2(wl.x); wl2[1] = dup2(wl.y); wl2[2] = dup2(wl.z); wl2[3] = dup2(wl.w);
            wr2[0] = dup2(wr.x); wr2[1] = dup2(wr.y); wr2[2] = dup2(wr.z); wr2[3] = dup2(wr.w);
            #pragma unroll
            for (int p = 0; p < 4; p++) {
                ull ap = Asp[k * SP + rpb + p];   // broadcast
                ull xp = Xsp[k * SP + rpb + p];   // broadcast
                acc[p][0] = fma2(ap, wl2[0], acc[p][0]);
                acc[p][1] = fma2(ap, wl2[1], acc[p][1]);
                acc[p][2] = fma2(ap, wl2[2], acc[p][2]);
                acc[p][3] = fma2(ap, wl2[3], acc[p][3]);
                acc[p][0] = fma2(xp, wr2[0], acc[p][0]);
                acc[p][1] = fma2(xp, wr2[1], acc[p][1]);
                acc[p][2] = fma2(xp, wr2[2], acc[p][2]);
                acc[p][3] = fma2(xp, wr2[3], acc[p][3]);
            }
        }
    }

    // ---- epilogue ----
    #pragma unroll
    for (int p = 0; p < 4; p++) {
        float re_[4], ro_[4];
        unpack2(acc[p][0], re_[0], ro_[0]);
        unpack2(acc[p][1], re_[1], ro_[1]);
        unpack2(acc[p][2], re_[2], ro_[2]);
        unpack2(acc[p][3], re_[3], ro_[3]);
        if (RELU) {
            #pragma unroll
            for (int j = 0; j < 4; j++) {
                re_[j] = fmaxf(re_[j], 0.0f);
                ro_[j] = fmaxf(ro_[j], 0.0f);
            }
        }
        int rowe = row0 + (rpb + p) * 2;
        if (rowe < NN)
            *reinterpret_cast<float4*>(out + (size_t)rowe * H + col) =
                make_float4(re_[0], re_[1], re_[2], re_[3]);
        if (rowe + 1 < NN)
            *reinterpret_cast<float4*>(out + (size_t)(rowe + 1) * H + col) =
                make_float4(ro_[0], ro_[1], ro_[2], ro_[3]);
    }
}

// ---------------- pool + MLP ----------------
#define POOL_CHUNK 64
__global__ void pool_kernel(const float* __restrict__ x, const int* __restrict__ batch) {
    int wid = (blockIdx.x * blockDim.x + threadIdx.x) >> 5;
    int lane = threadIdx.x & 31;
    int n0 = wid * POOL_CHUNK;
    if (n0 >= NN) return;
    int end = n0 + POOL_CHUNK;
    if (end > NN) end = NN;

    float4 acc = make_float4(0, 0, 0, 0);
    int cur = batch[n0];
    for (int n = n0; n < end; n++) {
        int b = batch[n];
        if (b != cur) {
            red4(g_pool + (size_t)cur * H + lane * 4, acc);
            acc = make_float4(0, 0, 0, 0);
            cur = b;
        }
        float4 v = *reinterpret_cast<const float4*>(x + (size_t)n * H + lane * 4);
        acc = f4add(acc, v);
    }
    red4(g_pool + (size_t)cur * H + lane * 4, acc);
}

__global__ void mlp_kernel(const float* __restrict__ W1, const float* __restrict__ b1,
                           const float* __restrict__ W2, const float* __restrict__ b2,
                           float* __restrict__ out) {
    __shared__ float gs[H];
    __shared__ float redv[4];
    int gid = blockIdx.x;
    int j = threadIdx.x;
    gs[j] = g_pool[(size_t)gid * H + j];
    __syncthreads();

    float acc = b1[j];
    #pragma unroll 4
    for (int k = 0; k < H; k++) acc += gs[k] * W1[k * H + j];
    float hv = fmaxf(acc, 0.0f) * W2[j];

    #pragma unroll
    for (int o = 16; o > 0; o >>= 1) hv += __shfl_down_sync(0xFFFFFFFFu, hv, o);
    if ((j & 31) == 0) redv[j >> 5] = hv;
    __syncthreads();
    if (j == 0) out[gid] = redv[0] + redv[1] + redv[2] + redv[3] + b2[0];
}

// ---------------- launch ----------------
extern "C" void kernel_launch(void* const* d_in, const int* in_sizes, int n_in,
                              void* d_out, int out_size) {
    const int*   z     = (const int*)d_in[0];
    const int*   ei    = (const int*)d_in[1];
    const int*   batch = (const int*)d_in[2];
    const float* z_emb = (const float*)d_in[3];
    const float* Wl0 = (const float*)d_in[4];
    const float* bl0 = (const float*)d_in[5];
    const float* Wr0 = (const float*)d_in[6];
    const float* Wl1 = (const float*)d_in[7];
    const float* bl1 = (const float*)d_in[8];
    const float* Wr1 = (const float*)d_in[9];
    const float* Wl2 = (const float*)d_in[10];
    const float* bl2 = (const float*)d_in[11];
    const float* Wr2 = (const float*)d_in[12];
    const float* W1  = (const float*)d_in[13];
    const float* b1  = (const float*)d_in[14];
    const float* W2  = (const float*)d_in[15];
    const float* b2  = (const float*)d_in[16];
    const int* src = ei;
    const int* dst = ei + NE;
    float* out = (float*)d_out;

    void *pxa_, *pxb_;
    cudaGetSymbolAddress(&pxa_, g_xa);
    cudaGetSymbolAddress(&pxb_, g_xb);
    float* xa = (float*)pxa_;
    float* xb = (float*)pxb_;

    cudaFuncSetAttribute((const void*)sage_layer_kernel<true>,
                         cudaFuncAttributeMaxDynamicSharedMemorySize, SMEM_BYTES);
    cudaFuncSetAttribute((const void*)sage_layer_kernel<false>,
                         cudaFuncAttributeMaxDynamicSharedMemorySize, SMEM_BYTES);

    const int gemm_blocks = (NN + 63) / 64;              // 782
    const int pool_warps  = (NN + POOL_CHUNK - 1) / POOL_CHUNK;
    const int pool_blocks = (pool_warps + 7) / 8;        // 8 warps/block

    // degree + CSR build (shared by all 3 layers)
    init_kernel<<<(NG * H + 255) / 256, 256>>>();
    deg_kernel<<<(NE + 255) / 256, 256>>>(dst);
    scan_kernel<<<1, SCAN_T>>>();
    fill_kernel<<<(NE + 255) / 256, 256>>>(src, dst);
    embed_kernel<<<(NN * 32 + 255) / 256, 256>>>(z, z_emb);

    // layers (gather fused into GEMM staging)
    sage_layer_kernel<true ><<<gemm_blocks, 256, SMEM_BYTES>>>(xa, Wl0, bl0, Wr0, xb);
    sage_layer_kernel<true ><<<gemm_blocks, 256, SMEM_BYTES>>>(xb, Wl1, bl1, Wr1, xa);
    sage_layer_kernel<false><<<gemm_blocks, 256, SMEM_BYTES>>>(xa, Wl2, bl2, Wr2, xb);

    // pool + MLP head
    pool_kernel<<<pool_blocks, 256>>>(xb, batch);
    mlp_kernel<<<NG, H>>>(W1, b1, W2, b2, out);
}

// round 13
// speedup vs baseline: 1.0341x; 1.0341x over previous
#include <cuda_runtime.h>
#include <string.h>

#define NN 50000
#define NE 800000
#define H  128
#define NG 512

typedef unsigned long long ull;

// ---------------- scratch (static device globals; no allocation) ----------------
__device__ int   g_degi[NN];
__device__ float g_deginv[NN];
__device__ int   g_rowptr[NN + 1];
__device__ int   g_cursor[NN];
__device__ int   g_esrc[NE];                      // CSR: source node per in-edge
__device__ float g_xa[(size_t)NN * H];
__device__ float g_xb[(size_t)NN * H];
__device__ float g_agg[(size_t)NN * H];
__device__ float g_pool[NG * H];

// ---------------- helpers ----------------
__device__ __forceinline__ void red4(float* p, float4 v) {
    asm volatile("red.global.add.v4.f32 [%0], {%1, %2, %3, %4};"
                 :: "l"(p), "f"(v.x), "f"(v.y), "f"(v.z), "f"(v.w) : "memory");
}

__device__ __forceinline__ ull dup2(float a) {
    ull r;
    asm("mov.b64 %0, {%1, %1};" : "=l"(r) : "f"(a));
    return r;
}

__device__ __forceinline__ ull fma2(ull a, ull b, ull c) {
    ull d;
    asm("fma.rn.f32x2 %0, %1, %2, %3;" : "=l"(d) : "l"(a), "l"(b), "l"(c));
    return d;
}

__device__ __forceinline__ float4 f4add(float4 a, float4 b) {
    return make_float4(a.x + b.x, a.y + b.y, a.z + b.z, a.w + b.w);
}

// ---------------- setup kernels ----------------

__global__ void init_kernel() {
    int i = blockIdx.x * blockDim.x + threadIdx.x;
    if (i < NN) g_degi[i] = 0;
    if (i < NG * H) g_pool[i] = 0.0f;   // NG*H = 65536 >= NN
}

__global__ void deg_kernel(const int* __restrict__ dst) {
    int e = blockIdx.x * blockDim.x + threadIdx.x;
    if (e < NE) atomicAdd(&g_degi[dst[e]], 1);
}

#define SCAN_T 1024
__global__ void scan_kernel() {
    __shared__ int sm[SCAN_T];
    int t = threadIdx.x;
    const int C = (NN + SCAN_T - 1) / SCAN_T;   // 49
    int b = t * C;
    int e = b + C; if (e > NN) e = NN;
    if (b > NN) b = NN;
    int s = 0;
    for (int i = b; i < e; i++) s += g_degi[i];
    sm[t] = s;
    __syncthreads();
    for (int off = 1; off < SCAN_T; off <<= 1) {
        int v = (t >= off) ? sm[t - off] : 0;
        __syncthreads();
        sm[t] += v;
        __syncthreads();
    }
    int base = (t > 0) ? sm[t - 1] : 0;   // exclusive prefix
    for (int i = b; i < e; i++) {
        g_rowptr[i] = base;
        g_cursor[i] = base;
        int d = g_degi[i];
        g_deginv[i] = 1.0f / fmaxf((float)d, 1.0f);
        base += d;
    }
    if (t == SCAN_T - 1) g_rowptr[NN] = base;
}

__global__ void fill_kernel(const int* __restrict__ src, const int* __restrict__ dst) {
    int e = blockIdx.x * blockDim.x + threadIdx.x;
    if (e < NE) {
        int p = atomicAdd(&g_cursor[dst[e]], 1);
        g_esrc[p] = src[e];
    }
}

__global__ void embed_kernel(const int* __restrict__ z, const float* __restrict__ z_emb) {
    int idx = blockIdx.x * blockDim.x + threadIdx.x;
    if (idx >= NN * 32) return;
    int node = idx >> 5, lane = idx & 31;
    float4 v = *reinterpret_cast<const float4*>(z_emb + (size_t)z[node] * H + lane * 4);
    *reinterpret_cast<float4*>(g_xa + (size_t)node * H + lane * 4) = v;
}

// ---------------- gather: agg[row] = deginv[row] * sum_{e in row} x[esrc[e]] ----
// Warp per row, no smem, high occupancy -> latency hidden, runs at LTS throughput.
__global__ void gather_kernel(const float* __restrict__ x) {
    int wid = (blockIdx.x * blockDim.x + threadIdx.x) >> 5;
    if (wid >= NN) return;
    int lane = threadIdx.x & 31;
    int col = lane * 4;

    float4 a0 = make_float4(0, 0, 0, 0);
    float4 a1 = a0, a2 = a0, a3 = a0;
    int beg = g_rowptr[wid];
    int end = g_rowptr[wid + 1];
    int e = beg;
    for (; e + 4 <= end; e += 4) {
        int s0 = g_esrc[e];
        int s1 = g_esrc[e + 1];
        int s2 = g_esrc[e + 2];
        int s3 = g_esrc[e + 3];
        a0 = f4add(a0, *reinterpret_cast<const float4*>(x + (size_t)s0 * H + col));
        a1 = f4add(a1, *reinterpret_cast<const float4*>(x + (size_t)s1 * H + col));
        a2 = f4add(a2, *reinterpret_cast<const float4*>(x + (size_t)s2 * H + col));
        a3 = f4add(a3, *reinterpret_cast<const float4*>(x + (size_t)s3 * H + col));
    }
    for (; e < end; e++) {
        int s0 = g_esrc[e];
        a0 = f4add(a0, *reinterpret_cast<const float4*>(x + (size_t)s0 * H + col));
    }
    float di = g_deginv[wid];
    a0 = f4add(f4add(a0, a1), f4add(a2, a3));
    a0.x *= di; a0.y *= di; a0.z *= di; a0.w *= di;
    *reinterpret_cast<float4*>(g_agg + (size_t)wid * H + col) = a0;
}

// ---------------- GEMM: out = act(agg @ Wl + bl + x @ Wr) ----------------
// R6-measured structure: 64 rows x 128 cols, 256 threads (8 warps x 8 rows),
// f32x2 packed FMA, k in pairs via LDS.64, W from global (L1-resident).
template <bool RELU>
__global__ void __launch_bounds__(256)
gemm_kernel(const float* __restrict__ x,
            const float* __restrict__ Wl,
            const float* __restrict__ bl,
            const float* __restrict__ Wr,
            float* __restrict__ out) {
    extern __shared__ float smf[];
    float* As = smf;            // 64 x 128
    float* Xs = smf + 64 * H;   // 64 x 128

    int row0 = blockIdx.x * 64;
    int tid = threadIdx.x;
    int lane = tid & 31;
    int w = tid >> 5;

    // stage As (pre-scaled agg) + Xs
    for (int i = tid; i < 64 * (H / 4); i += 256) {
        int r = i >> 5;
        int c4 = (i & 31) * 4;
        int row = row0 + r;
        float4 av = make_float4(0, 0, 0, 0);
        float4 xv = av;
        if (row < NN) {
            av = *reinterpret_cast<const float4*>(g_agg + (size_t)row * H + c4);
            xv = *reinterpret_cast<const float4*>(x + (size_t)row * H + c4);
        }
        *reinterpret_cast<float4*>(As + r * H + c4) = av;
        *reinterpret_cast<float4*>(Xs + r * H + c4) = xv;
    }
    __syncthreads();

    int col = lane * 4;   // this thread's 4 output columns
    int r0 = w * 8;       // this thread's 8 rows

    ulonglong2 acc[8];
    {
        ulonglong2 bv = *reinterpret_cast<const ulonglong2*>(bl + col);
        #pragma unroll
        for (int i = 0; i < 8; i++) acc[i] = bv;
    }

    #pragma unroll 2
    for (int k = 0; k < H; k += 2) {
        ulonglong2 wl0 = *reinterpret_cast<const ulonglong2*>(Wl + (k + 0) * H + col);
        ulonglong2 wl1 = *reinterpret_cast<const ulonglong2*>(Wl + (k + 1) * H + col);
        ulonglong2 wr0 = *reinterpret_cast<const ulonglong2*>(Wr + (k + 0) * H + col);
        ulonglong2 wr1 = *reinterpret_cast<const ulonglong2*>(Wr + (k + 1) * H + col);
        #pragma unroll
        for (int i = 0; i < 8; i++) {
            float2 a  = *reinterpret_cast<const float2*>(As + (r0 + i) * H + k);
            float2 xv = *reinterpret_cast<const float2*>(Xs + (r0 + i) * H + k);
            ull a20 = dup2(a.x),  a21 = dup2(a.y);
            ull x20 = dup2(xv.x), x21 = dup2(xv.y);
            acc[i].x = fma2(a20, wl0.x, acc[i].x);
            acc[i].y = fma2(a20, wl0.y, acc[i].y);
            acc[i].x = fma2(x20, wr0.x, acc[i].x);
            acc[i].y = fma2(x20, wr0.y, acc[i].y);
            acc[i].x = fma2(a21, wl1.x, acc[i].x);
            acc[i].y = fma2(a21, wl1.y, acc[i].y);
            acc[i].x = fma2(x21, wr1.x, acc[i].x);
            acc[i].y = fma2(x21, wr1.y, acc[i].y);
        }
    }

    #pragma unroll
    for (int i = 0; i < 8; i++) {
        int row = row0 + r0 + i;
        if (row < NN) {
            float4 v;
            memcpy(&v, &acc[i], 16);
            if (RELU) {
                v.x = fmaxf(v.x, 0.0f); v.y = fmaxf(v.y, 0.0f);
                v.z = fmaxf(v.z, 0.0f); v.w = fmaxf(v.w, 0.0f);
            }
            *reinterpret_cast<float4*>(out + (size_t)row * H + col) = v;
        }
    }
}

// ---------------- pool + MLP ----------------
#define POOL_CHUNK 64
__global__ void pool_kernel(const float* __restrict__ x, const int* __restrict__ batch) {
    int wid = (blockIdx.x * blockDim.x + threadIdx.x) >> 5;
    int lane = threadIdx.x & 31;
    int n0 = wid * POOL_CHUNK;
    if (n0 >= NN) return;
    int end = n0 + POOL_CHUNK;
    if (end > NN) end = NN;

    float4 acc = make_float4(0, 0, 0, 0);
    int cur = batch[n0];
    for (int n = n0; n < end; n++) {
        int b = batch[n];
        if (b != cur) {
            red4(g_pool + (size_t)cur * H + lane * 4, acc);
            acc = make_float4(0, 0, 0, 0);
            cur = b;
        }
        float4 v = *reinterpret_cast<const float4*>(x + (size_t)n * H + lane * 4);
        acc = f4add(acc, v);
    }
    red4(g_pool + (size_t)cur * H + lane * 4, acc);
}

__global__ void mlp_kernel(const float* __restrict__ W1, const float* __restrict__ b1,
                           const float* __restrict__ W2, const float* __restrict__ b2,
                           float* __restrict__ out) {
    __shared__ float gs[H];
    __shared__ float redv[4];
    int gid = blockIdx.x;
    int j = threadIdx.x;
    gs[j] = g_pool[(size_t)gid * H + j];
    __syncthreads();

    float acc = b1[j];
    #pragma unroll 4
    for (int k = 0; k < H; k++) acc += gs[k] * W1[k * H + j];
    float hv = fmaxf(acc, 0.0f) * W2[j];

    #pragma unroll
    for (int o = 16; o > 0; o >>= 1) hv += __shfl_down_sync(0xFFFFFFFFu, hv, o);
    if ((j & 31) == 0) redv[j >> 5] = hv;
    __syncthreads();
    if (j == 0) out[gid] = redv[0] + redv[1] + redv[2] + redv[3] + b2[0];
}

// ---------------- launch ----------------
extern "C" void kernel_launch(void* const* d_in, const int* in_sizes, int n_in,
                              void* d_out, int out_size) {
    const int*   z     = (const int*)d_in[0];
    const int*   ei    = (const int*)d_in[1];
    const int*   batch = (const int*)d_in[2];
    const float* z_emb = (const float*)d_in[3];
    const float* Wl0 = (const float*)d_in[4];
    const float* bl0 = (const float*)d_in[5];
    const float* Wr0 = (const float*)d_in[6];
    const float* Wl1 = (const float*)d_in[7];
    const float* bl1 = (const float*)d_in[8];
    const float* Wr1 = (const float*)d_in[9];
    const float* Wl2 = (const float*)d_in[10];
    const float* bl2 = (const float*)d_in[11];
    const float* Wr2 = (const float*)d_in[12];
    const float* W1  = (const float*)d_in[13];
    const float* b1  = (const float*)d_in[14];
    const float* W2  = (const float*)d_in[15];
    const float* b2  = (const float*)d_in[16];
    const int* src = ei;
    const int* dst = ei + NE;
    float* out = (float*)d_out;

    void *pxa_, *pxb_;
    cudaGetSymbolAddress(&pxa_, g_xa);
    cudaGetSymbolAddress(&pxb_, g_xb);
    float* xa = (float*)pxa_;
    float* xb = (float*)pxb_;

    const int SMEM = 64 * H * 2 * sizeof(float);  // 65536
    cudaFuncSetAttribute((const void*)gemm_kernel<true>,
                         cudaFuncAttributeMaxDynamicSharedMemorySize, SMEM);
    cudaFuncSetAttribute((const void*)gemm_kernel<false>,
                         cudaFuncAttributeMaxDynamicSharedMemorySize, SMEM);

    const int gemm_blocks   = (NN + 63) / 64;            // 782
    const int gather_blocks = (NN * 32 + 255) / 256;     // 6250
    const int pool_warps  = (NN + POOL_CHUNK - 1) / POOL_CHUNK;
    const int pool_blocks = (pool_warps + 7) / 8;        // 8 warps/block

    // degree + CSR build (shared by all 3 layers)
    init_kernel<<<(NG * H + 255) / 256, 256>>>();
    deg_kernel<<<(NE + 255) / 256, 256>>>(dst);
    scan_kernel<<<1, SCAN_T>>>();
    fill_kernel<<<(NE + 255) / 256, 256>>>(src, dst);
    embed_kernel<<<(NN * 32 + 255) / 256, 256>>>(z, z_emb);

    // layer 0
    gather_kernel<<<gather_blocks, 256>>>(xa);
    gemm_kernel<true ><<<gemm_blocks, 256, SMEM>>>(xa, Wl0, bl0, Wr0, xb);
    // layer 1
    gather_kernel<<<gather_blocks, 256>>>(xb);
    gemm_kernel<true ><<<gemm_blocks, 256, SMEM>>>(xb, Wl1, bl1, Wr1, xa);
    // layer 2
    gather_kernel<<<gather_blocks, 256>>>(xa);
    gemm_kernel<false><<<gemm_blocks, 256, SMEM>>>(xa, Wl2, bl2, Wr2, xb);

    // pool + MLP head
    pool_kernel<<<pool_blocks, 256>>>(xb, batch);
    mlp_kernel<<<NG, H>>>(W1, b1, W2, b2, out);
}